// round 12
// baseline (speedup 1.0000x reference)
#include <cuda_runtime.h>
#include <cuda_bf16.h>
#include <mma.h>

using namespace nvcuda;

#define BATCH 8
#define HW    4096
#define CH    512
#define NTOK  (BATCH * HW)   // 32768

#define QT 64      // Q rows per flash block
#define KT 128     // KV rows per tile
#define DC 128     // channel chunk
#define ATT_SCALE 0.044194173824159216f   // 512^-0.5

// ---------------- scratch (device globals; no allocation APIs) ----------------
__device__ float         g_psum  [64 * BATCH * CH];
__device__ float         g_psumsq[64 * BATCH * CH];
__device__ float         g_sc  [BATCH * CH];
__device__ float         g_sh  [BATCH * CH];
__device__ float         g_xn [(size_t)NTOK * CH];          // 64 MB (f32 residual)
__device__ __nv_bfloat16 g_xnb[(size_t)NTOK * CH];          // 32 MB
__device__ __nv_bfloat16 g_wq[CH * CH], g_wk[CH * CH], g_wv[CH * CH], g_wp[CH * CH];
__device__ __nv_bfloat16 g_q [(size_t)NTOK * CH];
__device__ __nv_bfloat16 g_k [(size_t)NTOK * CH];
__device__ __nv_bfloat16 g_v [(size_t)NTOK * CH];
__device__ __nv_bfloat16 g_ao[(size_t)NTOK * CH];

// ---------------- helpers ----------------
static __device__ __forceinline__ void st4bf(__nv_bfloat16* p, float a, float b, float c, float d) {
    __nv_bfloat162* q2 = (__nv_bfloat162*)p;
    q2[0] = __floats2bfloat162_rn(a, b);
    q2[1] = __floats2bfloat162_rn(c, d);
}

// ---------------- weight convert: f32 -> bf16 (4 weights at once) ----------------
__global__ void wconv_kernel(const float* __restrict__ wq, const float* __restrict__ wk,
                             const float* __restrict__ wv, const float* __restrict__ wp) {
    int i = blockIdx.x * blockDim.x + threadIdx.x;
    if (i >= CH * CH / 4) return;
    float4 a = ((const float4*)wq)[i];
    st4bf(g_wq + 4 * i, a.x, a.y, a.z, a.w);
    float4 b = ((const float4*)wk)[i];
    st4bf(g_wk + 4 * i, b.x, b.y, b.z, b.w);
    float4 c = ((const float4*)wv)[i];
    st4bf(g_wv + 4 * i, c.x, c.y, c.z, c.w);
    float4 d = ((const float4*)wp)[i];
    st4bf(g_wp + 4 * i, d.x, d.y, d.z, d.w);
}

// ---------------- groupnorm (instance norm) ----------------
__global__ void gn_partial_kernel(const float* __restrict__ x) {
    int b  = blockIdx.z;
    int ct = blockIdx.y;
    int st = blockIdx.x;
    int c  = ct * 128 + threadIdx.x;
    size_t base = ((size_t)b * HW + (size_t)st * 64) * CH + c;
    float s = 0.f, ss = 0.f;
#pragma unroll 8
    for (int r = 0; r < 64; r++) {
        float f = x[base + (size_t)r * CH];
        s += f; ss += f * f;
    }
    int idx = b * CH + c;
    g_psum  [st * (BATCH * CH) + idx] = s;
    g_psumsq[st * (BATCH * CH) + idx] = ss;
}

__global__ void gn_final_kernel(const float* __restrict__ gamma, const float* __restrict__ beta) {
    int idx = blockIdx.x * blockDim.x + threadIdx.x;
    if (idx >= BATCH * CH) return;
    int c = idx & (CH - 1);
    float s = 0.f, ss = 0.f;
#pragma unroll 8
    for (int st = 0; st < 64; st++) {
        s  += g_psum  [st * (BATCH * CH) + idx];
        ss += g_psumsq[st * (BATCH * CH) + idx];
    }
    float mean = s * (1.0f / HW);
    float var  = ss * (1.0f / HW) - mean * mean;
    float rstd = rsqrtf(var + 1e-3f);
    float sc = rstd * gamma[c];
    g_sc[idx] = sc;
    g_sh[idx] = beta[c] - mean * sc;
}

__global__ void gn_apply_kernel(const float* __restrict__ x) {
    size_t i = ((size_t)blockIdx.x * blockDim.x + threadIdx.x) * 4;
    int c0 = (int)(i & (CH - 1));
    int n  = (int)(i >> 9);
    int b  = n >> 12;
    int bc = b * CH + c0;
    float4 xv = *(const float4*)(x + i);
    float4 r;
    r.x = xv.x * g_sc[bc + 0] + g_sh[bc + 0];
    r.y = xv.y * g_sc[bc + 1] + g_sh[bc + 1];
    r.z = xv.z * g_sc[bc + 2] + g_sh[bc + 2];
    r.w = xv.w * g_sc[bc + 3] + g_sh[bc + 3];
    *(float4*)(g_xn + i) = r;
    st4bf(g_xnb + i, r.x, r.y, r.z, r.w);
}

// ---------------- bf16 wmma GEMM: [M,K] x [K,N] with fused epilogue ----------------
// OM == 1: out bf16 = acc + bias[col]
// OM == 2: out f32  = acc + bias[col] + resid[row*ldc+col]
template <int OM>
__global__ __launch_bounds__(256) void gemm_bf16_kernel(
    const __nv_bfloat16* __restrict__ A,
    const __nv_bfloat16* __restrict__ B,
    void* __restrict__ Cv,
    const float* __restrict__ bias,
    const float* __restrict__ resid,
    int M, int N, int K, int lda, int ldb, int ldc)
{
    constexpr int BM = 128, BN = 128, BK = 32, PAD = 8;

    const int mBase = blockIdx.y * BM;
    const int nBase = blockIdx.x * BN;

    __shared__ __nv_bfloat16 shA[2][BM][BK + PAD];          // 20480 B
    __shared__ __nv_bfloat16 shB[2][BK][BN + PAD];          // 17408 B
    __shared__ float         stage[8][16][20];              // 10240 B (ldm=20: mult of 4 elems)

    const int tid = threadIdx.x;
    const int wid = tid >> 5;
    const int lane = tid & 31;
    const int wm = wid & 3;
    const int wn = wid >> 2;
    const int m0 = wm * 32;
    const int n0 = wn * 64;

    wmma::fragment<wmma::accumulator, 16, 16, 16, float> cf[2][4];
#pragma unroll
    for (int i = 0; i < 2; i++)
#pragma unroll
        for (int j = 0; j < 4; j++) wmma::fill_fragment(cf[i][j], 0.0f);

    uint4 ra[2], rb[2];

    auto fetchA = [&](int t) {
        int kb = t * BK;
#pragma unroll
        for (int i = 0; i < 2; i++) {
            int id = tid + i * 256;
            int r = id >> 2, cc = (id & 3) * 8;
            ra[i] = *(const uint4*)(A + (size_t)(mBase + r) * lda + kb + cc);
        }
    };
    auto storeA = [&](int buf) {
#pragma unroll
        for (int i = 0; i < 2; i++) {
            int id = tid + i * 256;
            int r = id >> 2, cc = (id & 3) * 8;
            *(uint4*)&shA[buf][r][cc] = ra[i];
        }
    };
    auto fetchB = [&](int t) {
        int kb = t * BK;
#pragma unroll
        for (int i = 0; i < 2; i++) {
            int id = tid + i * 256;
            int r = id >> 4, cc = (id & 15) * 8;
            rb[i] = *(const uint4*)(B + (size_t)(kb + r) * ldb + nBase + cc);
        }
    };
    auto storeB = [&](int buf) {
#pragma unroll
        for (int i = 0; i < 2; i++) {
            int id = tid + i * 256;
            int r = id >> 4, cc = (id & 15) * 8;
            *(uint4*)&shB[buf][r][cc] = rb[i];
        }
    };
    auto compute = [&](int buf) {
#pragma unroll
        for (int ks = 0; ks < BK; ks += 16) {
            wmma::fragment<wmma::matrix_a, 16, 16, 16, __nv_bfloat16, wmma::row_major> af[2];
#pragma unroll
            for (int i = 0; i < 2; i++)
                wmma::load_matrix_sync(af[i], &shA[buf][m0 + i * 16][ks], BK + PAD);
#pragma unroll
            for (int j = 0; j < 4; j++) {
                wmma::fragment<wmma::matrix_b, 16, 16, 16, __nv_bfloat16, wmma::row_major> bf;
                wmma::load_matrix_sync(bf, &shB[buf][ks][n0 + j * 16], BN + PAD);
#pragma unroll
                for (int i = 0; i < 2; i++) wmma::mma_sync(cf[i][j], af[i], bf, cf[i][j]);
            }
        }
    };

    const int nk = K / BK;
    fetchA(0); fetchB(0);
    storeA(0); storeB(0);
    __syncthreads();
    for (int t = 0; t < nk; t++) {
        int cur = t & 1;
        if (t + 1 < nk) { fetchA(t + 1); fetchB(t + 1); }
        compute(cur);
        if (t + 1 < nk) {
            storeA(cur ^ 1); storeB(cur ^ 1);
            __syncthreads();
        }
    }

    // ---- fused epilogue via per-warp staging tile (ldm=20, WMMA-legal) ----
#pragma unroll
    for (int i = 0; i < 2; i++)
#pragma unroll
        for (int j = 0; j < 4; j++) {
            wmma::store_matrix_sync(&stage[wid][0][0], cf[i][j], 20, wmma::mem_row_major);
            __syncwarp();
#pragma unroll
            for (int t = 0; t < 8; t++) {
                int e = lane + t * 32;
                int r = e >> 4, c = e & 15;
                int row = mBase + m0 + i * 16 + r;
                int col = nBase + n0 + j * 16 + c;
                float v = stage[wid][r][c] + bias[col];
                if (OM == 1) {
                    ((__nv_bfloat16*)Cv)[(size_t)row * ldc + col] = __float2bfloat16(v);
                } else {
                    size_t o = (size_t)row * ldc + col;
                    ((float*)Cv)[o] = v + resid[o];
                }
            }
            __syncwarp();
        }
}

// ---------------- fused flash attention (no-max softmax; safe for this score scale) ----------------
struct FlashSmem {
    __nv_bfloat16 Qs[QT][520];        // 66.5 KB
    __nv_bfloat16 KVs[KT][136];       // 34.8 KB (K chunk then V chunk)
    float         Ss[QT][136];        // 34.8 KB
    __nv_bfloat16 Ps[QT][136];        // 17.4 KB
    float         Os[QT][132];        // 33.8 KB
    float         lsum[QT];
};

__global__ __launch_bounds__(256, 1) void flash_kernel(
    const __nv_bfloat16* __restrict__ Q,
    const __nv_bfloat16* __restrict__ K,
    const __nv_bfloat16* __restrict__ V,
    __nv_bfloat16* __restrict__ AO)
{
    extern __shared__ char smraw[];
    FlashSmem& sm = *reinterpret_cast<FlashSmem*>(smraw);
    const int b   = blockIdx.y;
    const int qt  = blockIdx.x;
    const int tid = threadIdx.x;
    const int wid = tid >> 5;
    const int qw  = wid >> 1;   // 0..3: Q-row group of 16
    const int hw_ = wid & 1;    // 0..1: col half

    const size_t bbase = (size_t)b * HW * CH;
    const __nv_bfloat16* Qb = Q + bbase + (size_t)qt * QT * CH;
    const __nv_bfloat16* Kb = K + bbase;
    const __nv_bfloat16* Vb = V + bbase;

    // load Q tile (64 x 512)
#pragma unroll
    for (int i = 0; i < 16; i++) {
        int idx = tid + i * 256;          // 4096 uint4
        int r = idx >> 6, c8 = (idx & 63) << 3;
        *(uint4*)&sm.Qs[r][c8] = *(const uint4*)(Qb + (size_t)r * CH + c8);
    }
    if (tid < QT) sm.lsum[tid] = 0.f;

    wmma::fragment<wmma::accumulator, 16, 16, 16, float> of[4][4];
#pragma unroll
    for (int c = 0; c < 4; c++)
#pragma unroll
        for (int j = 0; j < 4; j++) wmma::fill_fragment(of[c][j], 0.f);

    uint4 fetch[8];
    auto fetchKV = [&](const __nv_bfloat16* src) {    // 128 rows x 128 ch, row stride CH
#pragma unroll
        for (int i = 0; i < 8; i++) {
            int idx = tid + i * 256;
            int r = idx >> 4, c8 = (idx & 15) << 3;
            fetch[i] = *(const uint4*)(src + (size_t)r * CH + c8);
        }
    };
    auto stsKV = [&]() {
#pragma unroll
        for (int i = 0; i < 8; i++) {
            int idx = tid + i * 256;
            int r = idx >> 4, c8 = (idx & 15) << 3;
            *(uint4*)&sm.KVs[r][c8] = fetch[i];
        }
    };

    __syncthreads();

    for (int kt = 0; kt < HW / KT; kt++) {
        const __nv_bfloat16* Kt = Kb + (size_t)kt * KT * CH;
        const __nv_bfloat16* Vt = Vb + (size_t)kt * KT * CH;

        wmma::fragment<wmma::accumulator, 16, 16, 16, float> sf[4];
#pragma unroll
        for (int j = 0; j < 4; j++) wmma::fill_fragment(sf[j], 0.f);

        // ---- S = Q . K^T over 4 channel chunks ----
        fetchKV(Kt);
        stsKV();
        __syncthreads();
#pragma unroll
        for (int ck = 0; ck < 4; ck++) {
            if (ck < 3) fetchKV(Kt + (ck + 1) * DC);
#pragma unroll
            for (int kk = 0; kk < 8; kk++) {
                wmma::fragment<wmma::matrix_a, 16, 16, 16, __nv_bfloat16, wmma::row_major> af;
                wmma::load_matrix_sync(af, &sm.Qs[qw * 16][ck * DC + kk * 16], 520);
#pragma unroll
                for (int j = 0; j < 4; j++) {
                    wmma::fragment<wmma::matrix_b, 16, 16, 16, __nv_bfloat16, wmma::col_major> bf;
                    wmma::load_matrix_sync(bf, &sm.KVs[hw_ * 64 + j * 16][kk * 16], 136);
                    wmma::mma_sync(sf[j], af, bf, sf[j]);
                }
            }
            __syncthreads();
            if (ck < 3) { stsKV(); __syncthreads(); }
        }

        // prefetch V chunk 0 while doing softmax conversion
        fetchKV(Vt);

        // store S tile to smem (f32)
#pragma unroll
        for (int j = 0; j < 4; j++)
            wmma::store_matrix_sync(&sm.Ss[qw * 16][hw_ * 64 + j * 16], sf[j], 136,
                                    wmma::mem_row_major);
        __syncthreads();

        // exp + bf16 P + row-sum accumulation (no max subtraction; |s| << 1 here)
        {
            int r = tid >> 2, g = tid & 3;
            float part = 0.f;
#pragma unroll
            for (int c0 = 0; c0 < 32; c0++) {
                float e = __expf(sm.Ss[r][g * 32 + c0] * ATT_SCALE);
                part += e;
                sm.Ps[r][g * 32 + c0] = __float2bfloat16(e);
            }
            part += __shfl_xor_sync(0xffffffffu, part, 1);
            part += __shfl_xor_sync(0xffffffffu, part, 2);
            if (g == 0) sm.lsum[r] += part;
        }
        __syncthreads();

        // ---- O += P . V over 4 d chunks ----
        stsKV();               // V chunk 0 (fetched above)
        __syncthreads();
#pragma unroll
        for (int c = 0; c < 4; c++) {
            if (c < 3) fetchKV(Vt + (c + 1) * DC);
#pragma unroll
            for (int kk = 0; kk < 8; kk++) {
                wmma::fragment<wmma::matrix_a, 16, 16, 16, __nv_bfloat16, wmma::row_major> af;
                wmma::load_matrix_sync(af, &sm.Ps[qw * 16][kk * 16], 136);
#pragma unroll
                for (int j = 0; j < 4; j++) {
                    wmma::fragment<wmma::matrix_b, 16, 16, 16, __nv_bfloat16, wmma::row_major> bf;
                    wmma::load_matrix_sync(bf, &sm.KVs[kk * 16][hw_ * 64 + j * 16], 136);
                    wmma::mma_sync(of[c][j], af, bf, of[c][j]);
                }
            }
            __syncthreads();
            if (c < 3) { stsKV(); __syncthreads(); }
        }
    }

    // ---- normalize and write AO (bf16) ----
    __nv_bfloat16* AOb = AO + bbase + (size_t)qt * QT * CH;
#pragma unroll
    for (int c = 0; c < 4; c++) {
#pragma unroll
        for (int j = 0; j < 4; j++)
            wmma::store_matrix_sync(&sm.Os[qw * 16][hw_ * 64 + j * 16], of[c][j], 132,
                                    wmma::mem_row_major);
        __syncthreads();
#pragma unroll
        for (int i = 0; i < 32; i++) {
            int idx = tid + i * 256;     // 8192 elements
            int r = idx >> 7, cc = idx & 127;
            float val = sm.Os[r][cc] * (1.0f / sm.lsum[r]);
            AOb[(size_t)r * CH + c * DC + cc] = __float2bfloat16(val);
        }
        __syncthreads();
    }
}

// ---------------- launch ----------------
extern "C" void kernel_launch(void* const* d_in, const int* in_sizes, int n_in,
                              void* d_out, int out_size) {
    (void)in_sizes; (void)n_in; (void)out_size;
    const float* x     = (const float*)d_in[0];
    const float* gamma = (const float*)d_in[1];
    const float* beta  = (const float*)d_in[2];
    const float* Wq    = (const float*)d_in[3];
    const float* bq    = (const float*)d_in[4];
    const float* Wk    = (const float*)d_in[5];
    const float* bk    = (const float*)d_in[6];
    const float* Wv    = (const float*)d_in[7];
    const float* bv    = (const float*)d_in[8];
    const float* Wp    = (const float*)d_in[9];
    const float* bp    = (const float*)d_in[10];
    float* out = (float*)d_out;

    float *p_xn;
    __nv_bfloat16 *p_xnb, *p_wq, *p_wk, *p_wv, *p_wp, *p_q, *p_k, *p_v, *p_ao;
    cudaGetSymbolAddress((void**)&p_xn,  g_xn);
    cudaGetSymbolAddress((void**)&p_xnb, g_xnb);
    cudaGetSymbolAddress((void**)&p_wq,  g_wq);
    cudaGetSymbolAddress((void**)&p_wk,  g_wk);
    cudaGetSymbolAddress((void**)&p_wv,  g_wv);
    cudaGetSymbolAddress((void**)&p_wp,  g_wp);
    cudaGetSymbolAddress((void**)&p_q,   g_q);
    cudaGetSymbolAddress((void**)&p_k,   g_k);
    cudaGetSymbolAddress((void**)&p_v,   g_v);
    cudaGetSymbolAddress((void**)&p_ao,  g_ao);

    const int elemBlocks = (NTOK * CH / 4) / 256;   // 16384
    const dim3 ggrid(CH / 128, NTOK / 128, 1);

    wconv_kernel<<<(CH * CH / 4 + 255) / 256, 256>>>(Wq, Wk, Wv, Wp);
    gn_partial_kernel<<<dim3(64, 4, BATCH), 128>>>(x);
    gn_final_kernel<<<(BATCH * CH + 255) / 256, 256>>>(gamma, beta);
    gn_apply_kernel<<<elemBlocks, 256>>>(x);

    // Q/K/V projections with fused bias + bf16 store (attn scale folded into exp)
    gemm_bf16_kernel<1><<<ggrid, 256>>>(p_xnb, p_wq, p_q, bq, nullptr,
                                        NTOK, CH, CH, CH, CH, CH);
    gemm_bf16_kernel<1><<<ggrid, 256>>>(p_xnb, p_wk, p_k, bk, nullptr,
                                        NTOK, CH, CH, CH, CH, CH);
    gemm_bf16_kernel<1><<<ggrid, 256>>>(p_xnb, p_wv, p_v, bv, nullptr,
                                        NTOK, CH, CH, CH, CH, CH);

    // fused attention: AO = softmax(Q K^T * scale) V   (bf16 out)
    cudaFuncSetAttribute(flash_kernel, cudaFuncAttributeMaxDynamicSharedMemorySize,
                         (int)sizeof(FlashSmem));
    flash_kernel<<<dim3(HW / QT, BATCH), 256, sizeof(FlashSmem)>>>(p_q, p_k, p_v, p_ao);

    // OUT = AO @ Wp + bp + xn  (fused residual epilogue)
    gemm_bf16_kernel<2><<<ggrid, 256>>>(p_ao, p_wp, out, bp, p_xn,
                                        NTOK, CH, CH, CH, CH, CH);
}

// round 14
// speedup vs baseline: 1.5319x; 1.5319x over previous
#include <cuda_runtime.h>
#include <cuda_bf16.h>
#include <cstdint>

#define BATCH 8
#define HW    4096
#define CH    512
#define NTOK  (BATCH * HW)   // 32768
#define ATT_SCALE 0.044194173824159216f   // 512^-0.5

// ---------------- scratch (device globals; no allocation APIs) ----------------
__device__ __align__(256) float         g_psum  [64 * BATCH * CH];
__device__ __align__(256) float         g_psumsq[64 * BATCH * CH];
__device__ __align__(256) float         g_sc  [BATCH * CH];
__device__ __align__(256) float         g_sh  [BATCH * CH];
__device__ __align__(256) float         g_xn [(size_t)NTOK * CH];     // 64 MB (f32 residual)
__device__ __align__(256) __nv_bfloat16 g_xnb[(size_t)NTOK * CH];     // 32 MB
__device__ __align__(256) __nv_bfloat16 g_wq[CH * CH];
__device__ __align__(256) __nv_bfloat16 g_wk[CH * CH];
__device__ __align__(256) __nv_bfloat16 g_wv[CH * CH];
__device__ __align__(256) __nv_bfloat16 g_wp[CH * CH];
__device__ __align__(256) __nv_bfloat16 g_q [(size_t)NTOK * CH];
__device__ __align__(256) __nv_bfloat16 g_k [(size_t)NTOK * CH];
__device__ __align__(256) __nv_bfloat16 g_v [(size_t)NTOK * CH];
__device__ __align__(256) __nv_bfloat16 g_ao[(size_t)NTOK * CH];
__device__ __align__(256) __nv_bfloat16 g_S[(size_t)BATCH * HW * HW]; // 256 MB (S, then P in-place)

#include <mma.h>
using namespace nvcuda;

// ---------------- helpers ----------------
static __device__ __forceinline__ void st4bf(__nv_bfloat16* p, float a, float b, float c, float d) {
    __nv_bfloat162* q2 = (__nv_bfloat162*)p;
    q2[0] = __floats2bfloat162_rn(a, b);
    q2[1] = __floats2bfloat162_rn(c, d);
}

static __device__ __forceinline__ uint32_t smem_u32(const void* p) {
    uint32_t a;
    asm("{ .reg .u64 t; cvta.to.shared.u64 t, %1; cvt.u32.u64 %0, t; }" : "=r"(a) : "l"(p));
    return a;
}

static __device__ __forceinline__ void cp16(void* smem, const void* g) {
    asm volatile("cp.async.cg.shared.global [%0], [%1], 16;"
                 :: "r"(smem_u32(smem)), "l"(g));
}
static __device__ __forceinline__ void cp_commit() {
    asm volatile("cp.async.commit_group;" ::: "memory");
}

// ---------------- weight convert: f32 -> bf16 (4 weights at once) ----------------
__global__ void wconv_kernel(const float* __restrict__ wq, const float* __restrict__ wk,
                             const float* __restrict__ wv, const float* __restrict__ wp) {
    int i = blockIdx.x * blockDim.x + threadIdx.x;
    if (i >= CH * CH / 4) return;
    float4 a = ((const float4*)wq)[i];
    st4bf(g_wq + 4 * i, a.x, a.y, a.z, a.w);
    float4 b = ((const float4*)wk)[i];
    st4bf(g_wk + 4 * i, b.x, b.y, b.z, b.w);
    float4 c = ((const float4*)wv)[i];
    st4bf(g_wv + 4 * i, c.x, c.y, c.z, c.w);
    float4 d = ((const float4*)wp)[i];
    st4bf(g_wp + 4 * i, d.x, d.y, d.z, d.w);
}

// ---------------- groupnorm (instance norm) ----------------
__global__ void gn_partial_kernel(const float* __restrict__ x) {
    int b  = blockIdx.z;
    int ct = blockIdx.y;
    int st = blockIdx.x;
    int c  = ct * 128 + threadIdx.x;
    size_t base = ((size_t)b * HW + (size_t)st * 64) * CH + c;
    float s = 0.f, ss = 0.f;
#pragma unroll 8
    for (int r = 0; r < 64; r++) {
        float f = x[base + (size_t)r * CH];
        s += f; ss += f * f;
    }
    int idx = b * CH + c;
    g_psum  [st * (BATCH * CH) + idx] = s;
    g_psumsq[st * (BATCH * CH) + idx] = ss;
}

__global__ void gn_final_kernel(const float* __restrict__ gamma, const float* __restrict__ beta) {
    int idx = blockIdx.x * blockDim.x + threadIdx.x;
    if (idx >= BATCH * CH) return;
    int c = idx & (CH - 1);
    float s = 0.f, ss = 0.f;
#pragma unroll 8
    for (int st = 0; st < 64; st++) {
        s  += g_psum  [st * (BATCH * CH) + idx];
        ss += g_psumsq[st * (BATCH * CH) + idx];
    }
    float mean = s * (1.0f / HW);
    float var  = ss * (1.0f / HW) - mean * mean;
    float rstd = rsqrtf(var + 1e-3f);
    float sc = rstd * gamma[c];
    g_sc[idx] = sc;
    g_sh[idx] = beta[c] - mean * sc;
}

__global__ void gn_apply_kernel(const float* __restrict__ x) {
    size_t i = ((size_t)blockIdx.x * blockDim.x + threadIdx.x) * 4;
    int c0 = (int)(i & (CH - 1));
    int n  = (int)(i >> 9);
    int b  = n >> 12;
    int bc = b * CH + c0;
    float4 xv = *(const float4*)(x + i);
    float4 r;
    r.x = xv.x * g_sc[bc + 0] + g_sh[bc + 0];
    r.y = xv.y * g_sc[bc + 1] + g_sh[bc + 1];
    r.z = xv.z * g_sc[bc + 2] + g_sh[bc + 2];
    r.w = xv.w * g_sc[bc + 3] + g_sh[bc + 3];
    *(float4*)(g_xn + i) = r;
    st4bf(g_xnb + i, r.x, r.y, r.z, r.w);
}

// ---------------- bf16 wmma GEMM, BK=64, cp.async double-buffered ----------------
// C[M,N] = A[M,K] . B  ;  BT=false: B row-major [K,N]; BT=true: B row-major [N,K] (C = A.B^T)
// OM 0: bf16 plain    (S = QK^T, AO = PV)
// OM 1: bf16 + bias   (Q/K/V projections)
// OM 2: f32 + bias + resid (output projection)
#define BM 128
#define BN 128
#define BKk 64
#define APAD 8
#define SH_A_BYTES (2 * BM * (BKk + APAD) * 2)                 // 36864
template <int OM, bool BT>
__global__ __launch_bounds__(256) void gemm_bf16_kernel(
    const __nv_bfloat16* __restrict__ A,
    const __nv_bfloat16* __restrict__ B,
    void* __restrict__ Cv,
    const float* __restrict__ bias,
    const float* __restrict__ resid,
    int K, int lda, int ldb, int ldc,
    long long sA, long long sB, long long sC)
{
    extern __shared__ char dsm[];
    __nv_bfloat16* shA = (__nv_bfloat16*)dsm;                  // [2][128][72]
    __nv_bfloat16* shB = (__nv_bfloat16*)(dsm + SH_A_BYTES);   // BT:[2][128][72] else [2][64][136]
    float* stage = (float*)dsm;                                // reused post-mainloop

    A += (long long)blockIdx.z * sA;
    B += (long long)blockIdx.z * sB;
    const long long cOff = (long long)blockIdx.z * sC;

    const int mBase = blockIdx.y * BM;
    const int nBase = blockIdx.x * BN;
    const int tid  = threadIdx.x;
    const int wid  = tid >> 5;
    const int lane = tid & 31;
    const int m0 = (wid & 3) * 32;
    const int n0 = (wid >> 2) * 64;

    wmma::fragment<wmma::accumulator, 16, 16, 16, float> cf[2][4];
#pragma unroll
    for (int i = 0; i < 2; i++)
#pragma unroll
        for (int j = 0; j < 4; j++) wmma::fill_fragment(cf[i][j], 0.0f);

    auto cpTile = [&](int t, int buf) {
        int kb = t * BKk;
        __nv_bfloat16* dA = shA + buf * BM * (BKk + APAD);
#pragma unroll
        for (int i = 0; i < 4; i++) {
            int idx = tid + i * 256;
            int r = idx >> 3, c = (idx & 7) * 8;
            cp16(dA + r * (BKk + APAD) + c, A + (size_t)(mBase + r) * lda + kb + c);
        }
        if (BT) {
            __nv_bfloat16* dB = shB + buf * BN * (BKk + APAD);
#pragma unroll
            for (int i = 0; i < 4; i++) {
                int idx = tid + i * 256;
                int r = idx >> 3, c = (idx & 7) * 8;
                cp16(dB + r * (BKk + APAD) + c, B + (size_t)(nBase + r) * ldb + kb + c);
            }
        } else {
            __nv_bfloat16* dB = shB + buf * BKk * (BN + APAD);
#pragma unroll
            for (int i = 0; i < 4; i++) {
                int idx = tid + i * 256;
                int r = idx >> 4, c = (idx & 15) * 8;
                cp16(dB + r * (BN + APAD) + c, B + (size_t)(kb + r) * ldb + nBase + c);
            }
        }
    };

    auto compute = [&](int buf) {
        const __nv_bfloat16* Ab = shA + buf * BM * (BKk + APAD);
#pragma unroll
        for (int ks = 0; ks < BKk; ks += 16) {
            wmma::fragment<wmma::matrix_a, 16, 16, 16, __nv_bfloat16, wmma::row_major> af[2];
#pragma unroll
            for (int i = 0; i < 2; i++)
                wmma::load_matrix_sync(af[i], Ab + (m0 + i * 16) * (BKk + APAD) + ks, BKk + APAD);
            if constexpr (BT) {
                const __nv_bfloat16* Bb = shB + buf * BN * (BKk + APAD);
#pragma unroll
                for (int j = 0; j < 4; j++) {
                    wmma::fragment<wmma::matrix_b, 16, 16, 16, __nv_bfloat16, wmma::col_major> bf;
                    wmma::load_matrix_sync(bf, Bb + (n0 + j * 16) * (BKk + APAD) + ks, BKk + APAD);
#pragma unroll
                    for (int i = 0; i < 2; i++) wmma::mma_sync(cf[i][j], af[i], bf, cf[i][j]);
                }
            } else {
                const __nv_bfloat16* Bb = shB + buf * BKk * (BN + APAD);
#pragma unroll
                for (int j = 0; j < 4; j++) {
                    wmma::fragment<wmma::matrix_b, 16, 16, 16, __nv_bfloat16, wmma::row_major> bf;
                    wmma::load_matrix_sync(bf, Bb + ks * (BN + APAD) + n0 + j * 16, BN + APAD);
#pragma unroll
                    for (int i = 0; i < 2; i++) wmma::mma_sync(cf[i][j], af[i], bf, cf[i][j]);
                }
            }
        }
    };

    const int nk = K / BKk;
    cpTile(0, 0);
    cp_commit();
    for (int t = 0; t < nk; t++) {
        int buf = t & 1;
        if (t + 1 < nk) {
            cpTile(t + 1, buf ^ 1);
            cp_commit();
            asm volatile("cp.async.wait_group 1;" ::: "memory");
        } else {
            asm volatile("cp.async.wait_group 0;" ::: "memory");
        }
        __syncthreads();
        compute(buf);
        __syncthreads();
    }

    // ---- fused epilogue via per-warp staging tile (ldm=20, WMMA-legal) ----
    float* wstage = stage + wid * (16 * 20);
#pragma unroll
    for (int i = 0; i < 2; i++)
#pragma unroll
        for (int j = 0; j < 4; j++) {
            wmma::store_matrix_sync(wstage, cf[i][j], 20, wmma::mem_row_major);
            __syncwarp();
#pragma unroll
            for (int t = 0; t < 8; t++) {
                int e = lane + t * 32;
                int r = e >> 4, c = e & 15;
                int row = mBase + m0 + i * 16 + r;
                int col = nBase + n0 + j * 16 + c;
                float v = wstage[r * 20 + c];
                size_t o = (size_t)cOff + (size_t)row * ldc + col;
                if (OM == 0) {
                    ((__nv_bfloat16*)Cv)[o] = __float2bfloat16(v);
                } else if (OM == 1) {
                    ((__nv_bfloat16*)Cv)[o] = __float2bfloat16(v + bias[col]);
                } else {
                    ((float*)Cv)[o] = v + bias[col] + resid[o];
                }
            }
            __syncwarp();
        }
}

// ---------------- softmax per row (4096 cols), bf16 in-place, scale folded ----------------
__global__ __launch_bounds__(256) void softmax_kernel(__nv_bfloat16* __restrict__ S) {
    size_t row = blockIdx.x;
    __nv_bfloat162* p = (__nv_bfloat162*)(S + row * (size_t)HW);
    int tid = threadIdx.x;
    int lane = tid & 31, wid = tid >> 5;
    __shared__ float red[8];

    float v[16];
#pragma unroll
    for (int t = 0; t < 8; t++) {
        float2 f = __bfloat1622float2(p[tid + t * 256]);
        v[2 * t]     = f.x * ATT_SCALE;
        v[2 * t + 1] = f.y * ATT_SCALE;
    }

    float m = v[0];
#pragma unroll
    for (int t = 1; t < 16; t++) m = fmaxf(m, v[t]);
#pragma unroll
    for (int o = 16; o >= 1; o >>= 1) m = fmaxf(m, __shfl_xor_sync(0xffffffffu, m, o));
    if (lane == 0) red[wid] = m;
    __syncthreads();
    float bm = red[0];
#pragma unroll
    for (int w = 1; w < 8; w++) bm = fmaxf(bm, red[w]);
    __syncthreads();

    float sum = 0.f;
#pragma unroll
    for (int t = 0; t < 16; t++) { v[t] = __expf(v[t] - bm); sum += v[t]; }
#pragma unroll
    for (int o = 16; o >= 1; o >>= 1) sum += __shfl_xor_sync(0xffffffffu, sum, o);
    if (lane == 0) red[wid] = sum;
    __syncthreads();
    float bs = 0.f;
#pragma unroll
    for (int w = 0; w < 8; w++) bs += red[w];
    float inv = 1.0f / bs;
#pragma unroll
    for (int t = 0; t < 8; t++)
        p[tid + t * 256] = __floats2bfloat162_rn(v[2 * t] * inv, v[2 * t + 1] * inv);
}

// ---------------- launch ----------------
extern "C" void kernel_launch(void* const* d_in, const int* in_sizes, int n_in,
                              void* d_out, int out_size) {
    (void)in_sizes; (void)n_in; (void)out_size;
    const float* x     = (const float*)d_in[0];
    const float* gamma = (const float*)d_in[1];
    const float* beta  = (const float*)d_in[2];
    const float* Wq    = (const float*)d_in[3];
    const float* bq    = (const float*)d_in[4];
    const float* Wk    = (const float*)d_in[5];
    const float* bk    = (const float*)d_in[6];
    const float* Wv    = (const float*)d_in[7];
    const float* bv    = (const float*)d_in[8];
    const float* Wp    = (const float*)d_in[9];
    const float* bp    = (const float*)d_in[10];
    float* out = (float*)d_out;

    float *p_xn;
    __nv_bfloat16 *p_xnb, *p_wq, *p_wk, *p_wv, *p_wp, *p_q, *p_k, *p_v, *p_ao, *p_S;
    cudaGetSymbolAddress((void**)&p_xn,  g_xn);
    cudaGetSymbolAddress((void**)&p_xnb, g_xnb);
    cudaGetSymbolAddress((void**)&p_wq,  g_wq);
    cudaGetSymbolAddress((void**)&p_wk,  g_wk);
    cudaGetSymbolAddress((void**)&p_wv,  g_wv);
    cudaGetSymbolAddress((void**)&p_wp,  g_wp);
    cudaGetSymbolAddress((void**)&p_q,   g_q);
    cudaGetSymbolAddress((void**)&p_k,   g_k);
    cudaGetSymbolAddress((void**)&p_v,   g_v);
    cudaGetSymbolAddress((void**)&p_ao,  g_ao);
    cudaGetSymbolAddress((void**)&p_S,   g_S);

    const int elemBlocks = (NTOK * CH / 4) / 256;   // 16384
    const int GSMEM = SH_A_BYTES + 2 * BM * (BKk + APAD) * 2;  // 73728 (max of BT/noBT)

    cudaFuncSetAttribute(gemm_bf16_kernel<0, true>,
                         cudaFuncAttributeMaxDynamicSharedMemorySize, GSMEM);
    cudaFuncSetAttribute(gemm_bf16_kernel<0, false>,
                         cudaFuncAttributeMaxDynamicSharedMemorySize, GSMEM);
    cudaFuncSetAttribute(gemm_bf16_kernel<1, false>,
                         cudaFuncAttributeMaxDynamicSharedMemorySize, GSMEM);
    cudaFuncSetAttribute(gemm_bf16_kernel<2, false>,
                         cudaFuncAttributeMaxDynamicSharedMemorySize, GSMEM);

    wconv_kernel<<<(CH * CH / 4 + 255) / 256, 256>>>(Wq, Wk, Wv, Wp);
    gn_partial_kernel<<<dim3(64, 4, BATCH), 128>>>(x);
    gn_final_kernel<<<(BATCH * CH + 255) / 256, 256>>>(gamma, beta);
    gn_apply_kernel<<<elemBlocks, 256>>>(x);

    // Q/K/V projections: bf16 out + fused bias (attn scale folded into softmax)
    dim3 pg(CH / BN, NTOK / BM, 1);
    gemm_bf16_kernel<1, false><<<pg, 256, GSMEM>>>(p_xnb, p_wq, p_q, bq, nullptr,
                                                   CH, CH, CH, CH, 0, 0, 0);
    gemm_bf16_kernel<1, false><<<pg, 256, GSMEM>>>(p_xnb, p_wk, p_k, bk, nullptr,
                                                   CH, CH, CH, CH, 0, 0, 0);
    gemm_bf16_kernel<1, false><<<pg, 256, GSMEM>>>(p_xnb, p_wv, p_v, bv, nullptr,
                                                   CH, CH, CH, CH, 0, 0, 0);

    // S = Q . K^T (bf16 out, unscaled), batched
    gemm_bf16_kernel<0, true><<<dim3(HW / BN, HW / BM, BATCH), 256, GSMEM>>>(
        p_q, p_k, p_S, nullptr, nullptr,
        CH, CH, CH, HW,
        (long long)HW * CH, (long long)HW * CH, (long long)HW * HW);

    // P = softmax(S * scale), in-place on g_S
    softmax_kernel<<<NTOK, 256>>>(p_S);

    // AO = P . V (bf16 out), batched
    gemm_bf16_kernel<0, false><<<dim3(CH / BN, HW / BM, BATCH), 256, GSMEM>>>(
        p_S, p_v, p_ao, nullptr, nullptr,
        HW, HW, CH, CH,
        (long long)HW * HW, (long long)HW * CH, (long long)HW * CH);

    // OUT = AO @ Wp + bp + xn (fused residual epilogue)
    gemm_bf16_kernel<2, false><<<pg, 256, GSMEM>>>(p_ao, p_wp, out, bp, p_xn,
                                                   CH, CH, CH, CH, 0, 0, 0);
}

// round 15
// speedup vs baseline: 1.6672x; 1.0883x over previous
#include <cuda_runtime.h>
#include <cuda_bf16.h>
#include <cstdint>

#define BATCH 8
#define HW    4096
#define CH    512
#define NTOK  (BATCH * HW)   // 32768
#define ATT_SCALE 0.044194173824159216f   // 512^-0.5

// ---------------- scratch (device globals; no allocation APIs) ----------------
__device__ __align__(256) float         g_psum  [64 * BATCH * CH];
__device__ __align__(256) float         g_psumsq[64 * BATCH * CH];
__device__ __align__(256) float         g_sc  [BATCH * CH];
__device__ __align__(256) float         g_sh  [BATCH * CH];
__device__ __align__(256) float         g_xn [(size_t)NTOK * CH];     // 64 MB (f32 residual)
__device__ __align__(256) __nv_bfloat16 g_xnb[(size_t)NTOK * CH];     // 32 MB
__device__ __align__(256) __nv_bfloat16 g_wq[CH * CH];
__device__ __align__(256) __nv_bfloat16 g_wk[CH * CH];
__device__ __align__(256) __nv_bfloat16 g_wv[CH * CH];
__device__ __align__(256) __nv_bfloat16 g_wp[CH * CH];
__device__ __align__(256) __nv_bfloat16 g_q [(size_t)NTOK * CH];
__device__ __align__(256) __nv_bfloat16 g_k [(size_t)NTOK * CH];
__device__ __align__(256) __nv_bfloat16 g_v [(size_t)NTOK * CH];
__device__ __align__(256) __nv_bfloat16 g_ao[(size_t)NTOK * CH];
__device__ __align__(256) __nv_bfloat16 g_S[(size_t)BATCH * HW * HW]; // 256 MB (S, then P in-place)

#include <mma.h>
using namespace nvcuda;

// ---------------- helpers ----------------
static __device__ __forceinline__ void st4bf(__nv_bfloat16* p, float a, float b, float c, float d) {
    __nv_bfloat162* q2 = (__nv_bfloat162*)p;
    q2[0] = __floats2bfloat162_rn(a, b);
    q2[1] = __floats2bfloat162_rn(c, d);
}

static __device__ __forceinline__ uint32_t smem_u32(const void* p) {
    uint32_t a;
    asm("{ .reg .u64 t; cvta.to.shared.u64 t, %1; cvt.u32.u64 %0, t; }" : "=r"(a) : "l"(p));
    return a;
}

static __device__ __forceinline__ void cp16(void* smem, const void* g) {
    asm volatile("cp.async.cg.shared.global [%0], [%1], 16;"
                 :: "r"(smem_u32(smem)), "l"(g));
}
static __device__ __forceinline__ void cp_commit() {
    asm volatile("cp.async.commit_group;" ::: "memory");
}

// ---------------- weight convert: f32 -> bf16 (4 weights at once) ----------------
__global__ void wconv_kernel(const float* __restrict__ wq, const float* __restrict__ wk,
                             const float* __restrict__ wv, const float* __restrict__ wp) {
    int i = blockIdx.x * blockDim.x + threadIdx.x;
    if (i >= CH * CH / 4) return;
    float4 a = ((const float4*)wq)[i];
    st4bf(g_wq + 4 * i, a.x, a.y, a.z, a.w);
    float4 b = ((const float4*)wk)[i];
    st4bf(g_wk + 4 * i, b.x, b.y, b.z, b.w);
    float4 c = ((const float4*)wv)[i];
    st4bf(g_wv + 4 * i, c.x, c.y, c.z, c.w);
    float4 d = ((const float4*)wp)[i];
    st4bf(g_wp + 4 * i, d.x, d.y, d.z, d.w);
}

// ---------------- groupnorm (instance norm) ----------------
__global__ void gn_partial_kernel(const float* __restrict__ x) {
    int b  = blockIdx.z;
    int ct = blockIdx.y;
    int st = blockIdx.x;
    int c  = ct * 128 + threadIdx.x;
    size_t base = ((size_t)b * HW + (size_t)st * 64) * CH + c;
    float s = 0.f, ss = 0.f;
#pragma unroll 8
    for (int r = 0; r < 64; r++) {
        float f = x[base + (size_t)r * CH];
        s += f; ss += f * f;
    }
    int idx = b * CH + c;
    g_psum  [st * (BATCH * CH) + idx] = s;
    g_psumsq[st * (BATCH * CH) + idx] = ss;
}

__global__ void gn_final_kernel(const float* __restrict__ gamma, const float* __restrict__ beta) {
    int idx = blockIdx.x * blockDim.x + threadIdx.x;
    if (idx >= BATCH * CH) return;
    int c = idx & (CH - 1);
    float s = 0.f, ss = 0.f;
#pragma unroll 8
    for (int st = 0; st < 64; st++) {
        s  += g_psum  [st * (BATCH * CH) + idx];
        ss += g_psumsq[st * (BATCH * CH) + idx];
    }
    float mean = s * (1.0f / HW);
    float var  = ss * (1.0f / HW) - mean * mean;
    float rstd = rsqrtf(var + 1e-3f);
    float sc = rstd * gamma[c];
    g_sc[idx] = sc;
    g_sh[idx] = beta[c] - mean * sc;
}

__global__ void gn_apply_kernel(const float* __restrict__ x) {
    size_t i = ((size_t)blockIdx.x * blockDim.x + threadIdx.x) * 4;
    int c0 = (int)(i & (CH - 1));
    int n  = (int)(i >> 9);
    int b  = n >> 12;
    int bc = b * CH + c0;
    float4 xv = *(const float4*)(x + i);
    float4 r;
    r.x = xv.x * g_sc[bc + 0] + g_sh[bc + 0];
    r.y = xv.y * g_sc[bc + 1] + g_sh[bc + 1];
    r.z = xv.z * g_sc[bc + 2] + g_sh[bc + 2];
    r.w = xv.w * g_sc[bc + 3] + g_sh[bc + 3];
    *(float4*)(g_xn + i) = r;
    st4bf(g_xnb + i, r.x, r.y, r.z, r.w);
}

// ---------------- bf16 wmma GEMM, BK=64, 3-stage cp.async, 2 CTAs/SM ----------------
// C[M,N] = A[M,K] . B  ;  BT=false: B row-major [K,N]; BT=true: B row-major [N,K] (C = A.B^T)
// OM 0: bf16 plain    (S = QK^T, AO = PV)
// OM 1: bf16 + bias   (Q/K/V projections)
// OM 2: f32 + bias + resid (output projection)
#define BM 128
#define BN 128
#define BKk 64
#define APAD 8
#define STAGE_BYTES (BM * (BKk + APAD) * 2 * 2)      // A half + B half = 36864
#define A_HALF      (BM * (BKk + APAD) * 2)          // 18432
template <int OM, bool BT>
__global__ __launch_bounds__(256, 2) void gemm_bf16_kernel(
    const __nv_bfloat16* __restrict__ A,
    const __nv_bfloat16* __restrict__ B,
    void* __restrict__ Cv,
    const float* __restrict__ bias,
    const float* __restrict__ resid,
    int K, int lda, int ldb, int ldc,
    long long sA, long long sB, long long sC)
{
    extern __shared__ char dsm[];
    float* stage = (float*)dsm;                                // reused post-mainloop

    A += (long long)blockIdx.z * sA;
    B += (long long)blockIdx.z * sB;
    const long long cOff = (long long)blockIdx.z * sC;

    const int mBase = blockIdx.y * BM;
    const int nBase = blockIdx.x * BN;
    const int tid  = threadIdx.x;
    const int wid  = tid >> 5;
    const int lane = tid & 31;
    const int m0 = (wid & 3) * 32;
    const int n0 = (wid >> 2) * 64;

    wmma::fragment<wmma::accumulator, 16, 16, 16, float> cf[2][4];
#pragma unroll
    for (int i = 0; i < 2; i++)
#pragma unroll
        for (int j = 0; j < 4; j++) wmma::fill_fragment(cf[i][j], 0.0f);

    auto cpTile = [&](int t, int s) {
        int kb = t * BKk;
        __nv_bfloat16* dA = (__nv_bfloat16*)(dsm + s * STAGE_BYTES);
#pragma unroll
        for (int i = 0; i < 4; i++) {
            int idx = tid + i * 256;
            int r = idx >> 3, c = (idx & 7) * 8;
            cp16(dA + r * (BKk + APAD) + c, A + (size_t)(mBase + r) * lda + kb + c);
        }
        __nv_bfloat16* dB = (__nv_bfloat16*)(dsm + s * STAGE_BYTES + A_HALF);
        if (BT) {
#pragma unroll
            for (int i = 0; i < 4; i++) {
                int idx = tid + i * 256;
                int r = idx >> 3, c = (idx & 7) * 8;
                cp16(dB + r * (BKk + APAD) + c, B + (size_t)(nBase + r) * ldb + kb + c);
            }
        } else {
#pragma unroll
            for (int i = 0; i < 4; i++) {
                int idx = tid + i * 256;
                int r = idx >> 4, c = (idx & 15) * 8;
                cp16(dB + r * (BN + APAD) + c, B + (size_t)(kb + r) * ldb + nBase + c);
            }
        }
    };

    auto compute = [&](int s) {
        const __nv_bfloat16* Ab = (const __nv_bfloat16*)(dsm + s * STAGE_BYTES);
        const __nv_bfloat16* Bb = (const __nv_bfloat16*)(dsm + s * STAGE_BYTES + A_HALF);
#pragma unroll
        for (int ks = 0; ks < BKk; ks += 16) {
            wmma::fragment<wmma::matrix_a, 16, 16, 16, __nv_bfloat16, wmma::row_major> af[2];
#pragma unroll
            for (int i = 0; i < 2; i++)
                wmma::load_matrix_sync(af[i], Ab + (m0 + i * 16) * (BKk + APAD) + ks, BKk + APAD);
            if constexpr (BT) {
#pragma unroll
                for (int j = 0; j < 4; j++) {
                    wmma::fragment<wmma::matrix_b, 16, 16, 16, __nv_bfloat16, wmma::col_major> bf;
                    wmma::load_matrix_sync(bf, Bb + (n0 + j * 16) * (BKk + APAD) + ks, BKk + APAD);
#pragma unroll
                    for (int i = 0; i < 2; i++) wmma::mma_sync(cf[i][j], af[i], bf, cf[i][j]);
                }
            } else {
#pragma unroll
                for (int j = 0; j < 4; j++) {
                    wmma::fragment<wmma::matrix_b, 16, 16, 16, __nv_bfloat16, wmma::row_major> bf;
                    wmma::load_matrix_sync(bf, Bb + ks * (BN + APAD) + n0 + j * 16, BN + APAD);
#pragma unroll
                    for (int i = 0; i < 2; i++) wmma::mma_sync(cf[i][j], af[i], bf, cf[i][j]);
                }
            }
        }
    };

    const int nk = K / BKk;
    cpTile(0, 0); cp_commit();
    if (nk > 1) { cpTile(1, 1); cp_commit(); }

    int s = 0;
    for (int t = 0; t < nk; t++) {
        if (t + 1 < nk) {
            asm volatile("cp.async.wait_group 1;" ::: "memory");
        } else {
            asm volatile("cp.async.wait_group 0;" ::: "memory");
        }
        __syncthreads();           // stage t ready; all warps done computing stage (t-1)
        if (t + 2 < nk) {
            int sn = s + 2; if (sn >= 3) sn -= 3;
            cpTile(t + 2, sn);     // overwrites stage used at t-1: safe after the sync above
            cp_commit();
        }
        compute(s);
        if (++s == 3) s = 0;
    }
    __syncthreads();

    // ---- fused epilogue via per-warp staging tile (ldm=20, WMMA-legal) ----
    float* wstage = stage + wid * (16 * 20);
#pragma unroll
    for (int i = 0; i < 2; i++)
#pragma unroll
        for (int j = 0; j < 4; j++) {
            wmma::store_matrix_sync(wstage, cf[i][j], 20, wmma::mem_row_major);
            __syncwarp();
#pragma unroll
            for (int t = 0; t < 8; t++) {
                int e = lane + t * 32;
                int r = e >> 4, c = e & 15;
                int row = mBase + m0 + i * 16 + r;
                int col = nBase + n0 + j * 16 + c;
                float v = wstage[r * 20 + c];
                size_t o = (size_t)cOff + (size_t)row * ldc + col;
                if (OM == 0) {
                    ((__nv_bfloat16*)Cv)[o] = __float2bfloat16(v);
                } else if (OM == 1) {
                    ((__nv_bfloat16*)Cv)[o] = __float2bfloat16(v + bias[col]);
                } else {
                    ((float*)Cv)[o] = v + bias[col] + resid[o];
                }
            }
            __syncwarp();
        }
}

// ---------------- softmax per row (4096 cols), bf16 in-place, scale folded ----------------
__global__ __launch_bounds__(256) void softmax_kernel(__nv_bfloat16* __restrict__ S) {
    size_t row = blockIdx.x;
    __nv_bfloat162* p = (__nv_bfloat162*)(S + row * (size_t)HW);
    int tid = threadIdx.x;
    int lane = tid & 31, wid = tid >> 5;
    __shared__ float red[8];

    float v[16];
#pragma unroll
    for (int t = 0; t < 8; t++) {
        float2 f = __bfloat1622float2(p[tid + t * 256]);
        v[2 * t]     = f.x * ATT_SCALE;
        v[2 * t + 1] = f.y * ATT_SCALE;
    }

    float m = v[0];
#pragma unroll
    for (int t = 1; t < 16; t++) m = fmaxf(m, v[t]);
#pragma unroll
    for (int o = 16; o >= 1; o >>= 1) m = fmaxf(m, __shfl_xor_sync(0xffffffffu, m, o));
    if (lane == 0) red[wid] = m;
    __syncthreads();
    float bm = red[0];
#pragma unroll
    for (int w = 1; w < 8; w++) bm = fmaxf(bm, red[w]);
    __syncthreads();

    float sum = 0.f;
#pragma unroll
    for (int t = 0; t < 16; t++) { v[t] = __expf(v[t] - bm); sum += v[t]; }
#pragma unroll
    for (int o = 16; o >= 1; o >>= 1) sum += __shfl_xor_sync(0xffffffffu, sum, o);
    if (lane == 0) red[wid] = sum;
    __syncthreads();
    float bs = 0.f;
#pragma unroll
    for (int w = 0; w < 8; w++) bs += red[w];
    float inv = 1.0f / bs;
#pragma unroll
    for (int t = 0; t < 8; t++)
        p[tid + t * 256] = __floats2bfloat162_rn(v[2 * t] * inv, v[2 * t + 1] * inv);
}

// ---------------- launch ----------------
extern "C" void kernel_launch(void* const* d_in, const int* in_sizes, int n_in,
                              void* d_out, int out_size) {
    (void)in_sizes; (void)n_in; (void)out_size;
    const float* x     = (const float*)d_in[0];
    const float* gamma = (const float*)d_in[1];
    const float* beta  = (const float*)d_in[2];
    const float* Wq    = (const float*)d_in[3];
    const float* bq    = (const float*)d_in[4];
    const float* Wk    = (const float*)d_in[5];
    const float* bk    = (const float*)d_in[6];
    const float* Wv    = (const float*)d_in[7];
    const float* bv    = (const float*)d_in[8];
    const float* Wp    = (const float*)d_in[9];
    const float* bp    = (const float*)d_in[10];
    float* out = (float*)d_out;

    float *p_xn;
    __nv_bfloat16 *p_xnb, *p_wq, *p_wk, *p_wv, *p_wp, *p_q, *p_k, *p_v, *p_ao, *p_S;
    cudaGetSymbolAddress((void**)&p_xn,  g_xn);
    cudaGetSymbolAddress((void**)&p_xnb, g_xnb);
    cudaGetSymbolAddress((void**)&p_wq,  g_wq);
    cudaGetSymbolAddress((void**)&p_wk,  g_wk);
    cudaGetSymbolAddress((void**)&p_wv,  g_wv);
    cudaGetSymbolAddress((void**)&p_wp,  g_wp);
    cudaGetSymbolAddress((void**)&p_q,   g_q);
    cudaGetSymbolAddress((void**)&p_k,   g_k);
    cudaGetSymbolAddress((void**)&p_v,   g_v);
    cudaGetSymbolAddress((void**)&p_ao,  g_ao);
    cudaGetSymbolAddress((void**)&p_S,   g_S);

    const int elemBlocks = (NTOK * CH / 4) / 256;   // 16384
    const int GSMEM = 3 * STAGE_BYTES;              // 110592

    cudaFuncSetAttribute(gemm_bf16_kernel<0, true>,
                         cudaFuncAttributeMaxDynamicSharedMemorySize, GSMEM);
    cudaFuncSetAttribute(gemm_bf16_kernel<0, false>,
                         cudaFuncAttributeMaxDynamicSharedMemorySize, GSMEM);
    cudaFuncSetAttribute(gemm_bf16_kernel<1, false>,
                         cudaFuncAttributeMaxDynamicSharedMemorySize, GSMEM);
    cudaFuncSetAttribute(gemm_bf16_kernel<2, false>,
                         cudaFuncAttributeMaxDynamicSharedMemorySize, GSMEM);

    wconv_kernel<<<(CH * CH / 4 + 255) / 256, 256>>>(Wq, Wk, Wv, Wp);
    gn_partial_kernel<<<dim3(64, 4, BATCH), 128>>>(x);
    gn_final_kernel<<<(BATCH * CH + 255) / 256, 256>>>(gamma, beta);
    gn_apply_kernel<<<elemBlocks, 256>>>(x);

    // Q/K/V projections: bf16 out + fused bias (attn scale folded into softmax)
    dim3 pg(CH / BN, NTOK / BM, 1);
    gemm_bf16_kernel<1, false><<<pg, 256, GSMEM>>>(p_xnb, p_wq, p_q, bq, nullptr,
                                                   CH, CH, CH, CH, 0, 0, 0);
    gemm_bf16_kernel<1, false><<<pg, 256, GSMEM>>>(p_xnb, p_wk, p_k, bk, nullptr,
                                                   CH, CH, CH, CH, 0, 0, 0);
    gemm_bf16_kernel<1, false><<<pg, 256, GSMEM>>>(p_xnb, p_wv, p_v, bv, nullptr,
                                                   CH, CH, CH, CH, 0, 0, 0);

    // S = Q . K^T (bf16 out, unscaled), batched
    gemm_bf16_kernel<0, true><<<dim3(HW / BN, HW / BM, BATCH), 256, GSMEM>>>(
        p_q, p_k, p_S, nullptr, nullptr,
        CH, CH, CH, HW,
        (long long)HW * CH, (long long)HW * CH, (long long)HW * HW);

    // P = softmax(S * scale), in-place on g_S
    softmax_kernel<<<NTOK, 256>>>(p_S);

    // AO = P . V (bf16 out), batched
    gemm_bf16_kernel<0, false><<<dim3(CH / BN, HW / BM, BATCH), 256, GSMEM>>>(
        p_S, p_v, p_ao, nullptr, nullptr,
        HW, HW, CH, CH,
        (long long)HW * HW, (long long)HW * CH, (long long)HW * CH);

    // OUT = AO @ Wp + bp + xn (fused residual epilogue)
    gemm_bf16_kernel<2, false><<<pg, 256, GSMEM>>>(p_ao, p_wp, out, bp, p_xn,
                                                   CH, CH, CH, CH, 0, 0, 0);
}